// round 15
// baseline (speedup 1.0000x reference)
#include <cuda_runtime.h>
#include <cuda_fp16.h>
#include <cstdint>

#define D      1024
#define NHEAD  16
#define HDIM   64
#define BATCH  4
#define SEQ    2048
#define MTOT   (BATCH*SEQ)   // 8192

// ---------------- scratch (__device__ globals; no allocation allowed) ------
__device__ __half g_xf[(size_t)MTOT * D];          // x as fp16
__device__ __half g_cth[(size_t)MTOT * D];         // ctx as fp16 (attn output)
__device__ __half g_wh[4][(size_t)D * D];          // W^T fp16 [n][k]: 0=q 1=k 2=v 3=o

__device__ __half g_qh[(size_t)MTOT * D];          // Q fp16, scale folded
__device__ __half g_kh[(size_t)MTOT * D];          // K fp16
__device__ __half g_vh[(size_t)MTOT * D];          // V fp16 (row-major [tok][hd])

// ---------------- small helpers --------------------------------------------
__device__ __forceinline__ uint32_t smem_u32(const void* p) {
    return (uint32_t)__cvta_generic_to_shared(p);
}
__device__ __forceinline__ void cp16(uint32_t dst, const void* src) {
    asm volatile("cp.async.cg.shared.global [%0], [%1], 16;" :: "r"(dst), "l"(src) : "memory");
}
#define CP_COMMIT() asm volatile("cp.async.commit_group;" ::: "memory")
#define CP_WAIT0()  asm volatile("cp.async.wait_group 0;" ::: "memory")
#define CP_WAIT1()  asm volatile("cp.async.wait_group 1;" ::: "memory")

__device__ __forceinline__ void ldsm4(uint32_t* r, uint32_t a) {
    asm volatile("ldmatrix.sync.aligned.m8n8.x4.shared.b16 {%0,%1,%2,%3}, [%4];"
        : "=r"(r[0]), "=r"(r[1]), "=r"(r[2]), "=r"(r[3]) : "r"(a));
}
__device__ __forceinline__ void ldsm4t(uint32_t* r, uint32_t a) {
    asm volatile("ldmatrix.sync.aligned.m8n8.x4.trans.shared.b16 {%0,%1,%2,%3}, [%4];"
        : "=r"(r[0]), "=r"(r[1]), "=r"(r[2]), "=r"(r[3]) : "r"(a));
}
__device__ __forceinline__ void mma_f16(float* c, uint32_t a0, uint32_t a1, uint32_t a2,
                                        uint32_t a3, uint32_t b0, uint32_t b1) {
    asm volatile(
        "mma.sync.aligned.m16n8k16.row.col.f32.f16.f16.f32 "
        "{%0,%1,%2,%3}, {%4,%5,%6,%7}, {%8,%9}, {%0,%1,%2,%3};"
        : "+f"(c[0]), "+f"(c[1]), "+f"(c[2]), "+f"(c[3])
        : "r"(a0), "r"(a1), "r"(a2), "r"(a3), "r"(b0), "r"(b1));
}
__device__ __forceinline__ uint32_t pack_h2(float a, float b) {
    __half2 h = __floats2half2_rn(a, b);
    return *reinterpret_cast<uint32_t*>(&h);
}
__device__ __forceinline__ uint32_t ex2_h2(float a, float b) {
    uint32_t r = pack_h2(a, b);
    asm("ex2.approx.f16x2 %0, %0;" : "+r"(r));
    return r;
}

// ---------------- fused conversions (one launch) ----------------------------
__global__ void __launch_bounds__(256) conv_all(const float* __restrict__ x,
                                                const float* __restrict__ Wq,
                                                const float* __restrict__ Wk,
                                                const float* __restrict__ Wv,
                                                const float* __restrict__ Wo)
{
    int bid = blockIdx.x;
    if (bid < 4096) {
        int zW = bid >> 10;
        int yW = (bid >> 5) & 31;
        int xW = bid & 31;
        const float* W = (zW == 0) ? Wq : (zW == 1) ? Wk : (zW == 2) ? Wv : Wo;
        __half* th = g_wh[zW];

        __shared__ float t[32][33];
        int n0 = xW * 32, k0 = yW * 32;
        int tx = threadIdx.x & 31, ty = threadIdx.x >> 5;
#pragma unroll
        for (int i = 0; i < 4; i++)
            t[ty + i * 8][tx] = W[(size_t)(k0 + ty + i * 8) * D + n0 + tx];
        __syncthreads();
#pragma unroll
        for (int i = 0; i < 4; i++)
            th[(size_t)(n0 + ty + i * 8) * D + k0 + tx] = __float2half(t[tx][ty + i * 8]);
    } else {
        int i = (bid - 4096) * 256 + threadIdx.x;
        float4 v = ((const float4*)x)[i];
        uint2 o;
        o.x = pack_h2(v.x, v.y);
        o.y = pack_h2(v.z, v.w);
        ((uint2*)g_xf)[i] = o;
    }
}

// ---------------- mma.sync fp16 GEMM: 256x128 per CTA, shared W/B-frags -----
// CTA computes TWO 128-row m-tiles sharing one W tile. B fragments loaded
// once per (ks,p) feed both m-tiles: 8 LDSM -> 32 MMAs per ks (ratio 4.0).
// stage = A0 + A1 + W = 48 KB; 2 stages = 96 KB; 1 CTA/SM, 8 warps.
#define GTILE_B  (128 * 128)             // 16384 (128 rows x 128 bytes)
#define GSTG_B   (3 * GTILE_B)           // 49152 (A0, A1, W)
#define GSMEM    (2 * GSTG_B)            // 98304 (double buffered)

#define QSCALE (0.125f * 1.4426950408889634f)

template<int MODE>   // 0 = QKV (blockIdx.z picks), 1 = out-proj
__global__ void __launch_bounds__(256, 1) gemm_mma(float* __restrict__ outp,
                                                   const float* __restrict__ bias)
{
    extern __shared__ char sm[];
    const uint32_t smb = smem_u32(sm);
    const int tid = threadIdx.x;
    const int wid = tid >> 5, lane = tid & 31;
    const int g = lane >> 2, tg = lane & 3;
    const int wm = wid & 3, wn = wid >> 2;
    const int n0 = blockIdx.x * 128, m0 = blockIdx.y * 256;
    const int z = (MODE == 0) ? blockIdx.z : 3;

    const int am  = (lane & 7) + ((lane >> 3) & 1) * 8;
    const int akh = ((lane >> 4) & 1) * 16;
    const int bn  = (lane & 7) + ((lane >> 4) & 1) * 8;
    const int bkh = ((lane >> 3) & 1) * 16;
    const uint32_t kxorA = (uint32_t)(am & 7) << 4;
    const uint32_t kxorB = (uint32_t)(bn & 7) << 4;

    uint32_t koa[4], kob[4];
#pragma unroll
    for (int ks = 0; ks < 4; ks++) {
        koa[ks] = (uint32_t)(ks * 32 + akh) ^ kxorA;
        kob[ks] = (uint32_t)(ks * 32 + bkh) ^ kxorB;
    }

    const __half* srcA = ((MODE == 0) ? g_xf : g_cth) + (size_t)m0 * D;
    const __half* src3[3] = { srcA, srcA + (size_t)128 * D,
                              g_wh[z] + (size_t)n0 * D };

    // per stage: 3 tiles x 128 rows x 8 chunks = 3072 chunks, 12 per thread
    auto load_stage = [&](int kb, int st) {
#pragma unroll
        for (int i = 0; i < 12; i++) {
            int idx = tid + i * 256;
            int t   = idx >> 10;
            int rid = (idx >> 3) & 127;
            int c   = idx & 7;
            uint32_t dst = smb + st * GSTG_B + t * GTILE_B + rid * 128
                         + ((uint32_t)(c * 16) ^ ((uint32_t)(rid & 7) << 4));
            cp16(dst, src3[t] + (size_t)rid * D + kb * 64 + c * 8);
        }
    };

    float acc[4][8][4];   // [tile*2 + i][n-j][c]
#pragma unroll
    for (int i = 0; i < 4; i++)
#pragma unroll
        for (int j = 0; j < 8; j++)
#pragma unroll
            for (int c = 0; c < 4; c++) acc[i][j][c] = 0.f;

    load_stage(0, 0); CP_COMMIT();

    for (int kb = 0; kb < 16; kb++) {
        const int st = kb & 1;

        CP_WAIT0();          // only pending group = loads for kb
        __syncthreads();     // publish stage st; all reads of st^1 complete

        if (kb + 1 < 16) { load_stage(kb + 1, st ^ 1); CP_COMMIT(); }

        const uint32_t sa0 = smb + st * GSTG_B + (uint32_t)(wm * 32 + am) * 128;
        const uint32_t sa1 = sa0 + GTILE_B;
        const uint32_t sw  = smb + st * GSTG_B + 2 * GTILE_B
                           + (uint32_t)(wn * 64 + bn) * 128;

#pragma unroll
        for (int ks = 0; ks < 4; ks++) {
            uint32_t aF[4][4];     // [tile*2 + i]
#pragma unroll
            for (int i = 0; i < 2; i++) {
                ldsm4(aF[i],     sa0 + (uint32_t)(i * 16) * 128 + koa[ks]);
                ldsm4(aF[2 + i], sa1 + (uint32_t)(i * 16) * 128 + koa[ks]);
            }
#pragma unroll
            for (int p = 0; p < 4; p++) {
                uint32_t bF[4];
                ldsm4(bF, sw + (uint32_t)(p * 16) * 128 + kob[ks]);
#pragma unroll
                for (int i = 0; i < 4; i++) {
                    mma_f16(acc[i][2 * p],     aF[i][0], aF[i][1], aF[i][2], aF[i][3], bF[0], bF[1]);
                    mma_f16(acc[i][2 * p + 1], aF[i][0], aF[i][1], aF[i][2], aF[i][3], bF[2], bF[3]);
                }
            }
        }
    }

    // epilogue (two m-tiles)
#pragma unroll
    for (int i = 0; i < 4; i++) {
        const int tile = i >> 1, sub = i & 1;
#pragma unroll
        for (int j = 0; j < 8; j++) {
            int row = m0 + tile * 128 + wm * 32 + sub * 16 + g;
            int col = n0 + wn * 64 + j * 8 + tg * 2;
            float v0 = acc[i][j][0], v1 = acc[i][j][1];
            float v2 = acc[i][j][2], v3 = acc[i][j][3];
            if (MODE == 0) {
                if (z == 0) {
                    v0 *= QSCALE; v1 *= QSCALE; v2 *= QSCALE; v3 *= QSCALE;
                    *(uint32_t*)&g_qh[(size_t)row * D + col]       = pack_h2(v0, v1);
                    *(uint32_t*)&g_qh[(size_t)(row + 8) * D + col] = pack_h2(v2, v3);
                } else if (z == 1) {
                    *(uint32_t*)&g_kh[(size_t)row * D + col]       = pack_h2(v0, v1);
                    *(uint32_t*)&g_kh[(size_t)(row + 8) * D + col] = pack_h2(v2, v3);
                } else {
                    *(uint32_t*)&g_vh[(size_t)row * D + col]       = pack_h2(v0, v1);
                    *(uint32_t*)&g_vh[(size_t)(row + 8) * D + col] = pack_h2(v2, v3);
                }
            } else {
                float b0 = bias[col], b1 = bias[col + 1];
                *(float2*)&outp[(size_t)row * D + col]       = make_float2(v0 + b0, v1 + b1);
                *(float2*)&outp[(size_t)(row + 8) * D + col] = make_float2(v2 + b0, v3 + b1);
            }
        }
    }
}

// ---------------- FlashAttention-2 (round-12: 32-row warps + 3-stage ring) --
#define APITCH  144
#define AQ_B    (128 * APITCH)          // 18432
#define AKV_B   (64 * APITCH)           // 9216
#define ASTAGE  (2 * AKV_B)             // 18432
#define ASMEM   (AQ_B + 3 * ASTAGE)     // 73728 (Q + 3-stage ring)
#define ONES_H2 0x3C003C00u

__global__ void __launch_bounds__(128, 2) attn_mma()
{
    extern __shared__ char sm[];
    const uint32_t smb = smem_u32(sm);
    const int tid = threadIdx.x, wid = tid >> 5, lane = tid & 31;
    const int g = lane >> 2, tg = lane & 3;
    const int mb = gridDim.x - 1 - blockIdx.x;   // heavy CTAs first
    const int h = blockIdx.y, b = blockIdx.z;
    const int m0 = mb * 128, bS = b * SEQ;
    const int nt = 2 * mb + 2;

    const uint32_t aoff = (uint32_t)((lane & 7) + ((lane >> 3) & 1) * 8) * APITCH
                        + ((lane >> 4) & 1) * 16;
    const uint32_t boff = (uint32_t)((lane & 7) + ((lane >> 4) & 1) * 8) * APITCH
                        + ((lane >> 3) & 1) * 16;

    const __half* Qg = g_qh + (size_t)(bS + m0) * D + h * 64;
    const __half* Kg = g_kh + (size_t)bS * D + h * 64;
    const __half* Vg = g_vh + (size_t)bS * D + h * 64;

    auto load_tile = [&](int kt, int st) {
        int n0 = kt * 64;
#pragma unroll
        for (int i = 0; i < 4; i++) {
            int idx = tid + i * 128;
            int rid = idx >> 3, c = idx & 7;
            cp16(smb + AQ_B + st * ASTAGE + rid * APITCH + c * 16,
                 Kg + (size_t)(n0 + rid) * D + c * 8);
            cp16(smb + AQ_B + st * ASTAGE + AKV_B + rid * APITCH + c * 16,
                 Vg + (size_t)(n0 + rid) * D + c * 8);
        }
    };

#pragma unroll
    for (int i = 0; i < 8; i++) {
        int idx = tid + i * 128;
        int rid = idx >> 3, c = idx & 7;
        cp16(smb + rid * APITCH + c * 16, Qg + (size_t)rid * D + c * 8);
    }
    load_tile(0, 0); CP_COMMIT();      // group0 = Q + tile0
    load_tile(1, 1); CP_COMMIT();      // group1 = tile1
    CP_WAIT1();                        // Q + tile0 ready
    __syncthreads();

    uint32_t qf0[4][4], qf1[4][4];
    {
        uint32_t q0 = smb + (uint32_t)(wid * 32) * APITCH + aoff;
        uint32_t q1 = q0 + 16 * APITCH;
#pragma unroll
        for (int ks = 0; ks < 4; ks++) {
            ldsm4(qf0[ks], q0 + ks * 32);
            ldsm4(qf1[ks], q1 + ks * 32);
        }
    }

    float oacc0[8][4], oacc1[8][4];
#pragma unroll
    for (int j = 0; j < 8; j++)
#pragma unroll
        for (int c = 0; c < 4; c++) { oacc0[j][c] = 0.f; oacc1[j][c] = 0.f; }
    float mpA0 = -1e30f, mpA1 = -1e30f, mpB0 = -1e30f, mpB1 = -1e30f;
    float lsA0 = 0.f, lsA1 = 0.f, lsB0 = 0.f, lsB1 = 0.f;

    const int rA0 = m0 + wid * 32 + g;
    const int rA1 = rA0 + 8;
    const int rB0 = rA0 + 16;
    const int rB1 = rA0 + 24;

    for (int kt = 0; kt < nt; kt++) {
        if (kt + 2 < nt) { load_tile(kt + 2, (kt + 2) % 3); CP_COMMIT(); }

        const uint32_t kb = smb + AQ_B + (uint32_t)(kt % 3) * ASTAGE;
        const uint32_t vb = kb + AKV_B;

        float s0[8][4], s1[8][4];
#pragma unroll
        for (int j = 0; j < 8; j++)
#pragma unroll
            for (int c = 0; c < 4; c++) { s0[j][c] = 0.f; s1[j][c] = 0.f; }

#pragma unroll
        for (int ks = 0; ks < 4; ks++) {
#pragma unroll
            for (int p = 0; p < 4; p++) {
                uint32_t kf[4];
                ldsm4(kf, kb + (uint32_t)(p * 16) * APITCH + ks * 32 + boff);
                mma_f16(s0[2 * p],     qf0[ks][0], qf0[ks][1], qf0[ks][2], qf0[ks][3], kf[0], kf[1]);
                mma_f16(s0[2 * p + 1], qf0[ks][0], qf0[ks][1], qf0[ks][2], qf0[ks][3], kf[2], kf[3]);
                mma_f16(s1[2 * p],     qf1[ks][0], qf1[ks][1], qf1[ks][2], qf1[ks][3], kf[0], kf[1]);
                mma_f16(s1[2 * p + 1], qf1[ks][0], qf1[ks][1], qf1[ks][2], qf1[ks][3], kf[2], kf[3]);
            }
        }

        const int n0k = kt * 64;
        if (n0k + 63 > rA0) {
#pragma unroll
            for (int j = 0; j < 8; j++) {
                int c0 = n0k + j * 8 + tg * 2;
                if (c0 > rA0)     s0[j][0] = -1e30f;
                if (c0 + 1 > rA0) s0[j][1] = -1e30f;
                if (c0 > rA1)     s0[j][2] = -1e30f;
                if (c0 + 1 > rA1) s0[j][3] = -1e30f;
            }
        }
        if (n0k + 63 > rB0) {
#pragma unroll
            for (int j = 0; j < 8; j++) {
                int c0 = n0k + j * 8 + tg * 2;
                if (c0 > rB0)     s1[j][0] = -1e30f;
                if (c0 + 1 > rB0) s1[j][1] = -1e30f;
                if (c0 > rB1)     s1[j][2] = -1e30f;
                if (c0 + 1 > rB1) s1[j][3] = -1e30f;
            }
        }

        uint32_t ph0[8][2], ph1[8][2];
        float alA0, alA1;
        {
            float mx0 = -1e30f, mx1 = -1e30f;
#pragma unroll
            for (int j = 0; j < 8; j++) {
                mx0 = fmaxf(mx0, fmaxf(s0[j][0], s0[j][1]));
                mx1 = fmaxf(mx1, fmaxf(s0[j][2], s0[j][3]));
            }
            mx0 = fmaxf(mx0, __shfl_xor_sync(0xffffffffu, mx0, 1));
            mx0 = fmaxf(mx0, __shfl_xor_sync(0xffffffffu, mx0, 2));
            mx1 = fmaxf(mx1, __shfl_xor_sync(0xffffffffu, mx1, 1));
            mx1 = fmaxf(mx1, __shfl_xor_sync(0xffffffffu, mx1, 2));
            float mn0 = fmaxf(mpA0, mx0), mn1 = fmaxf(mpA1, mx1);
            alA0 = exp2f(mpA0 - mn0); alA1 = exp2f(mpA1 - mn1);
            mpA0 = mn0; mpA1 = mn1;
#pragma unroll
            for (int j = 0; j < 8; j++) {
                ph0[j][0] = ex2_h2(s0[j][0] - mn0, s0[j][1] - mn0);
                ph0[j][1] = ex2_h2(s0[j][2] - mn1, s0[j][3] - mn1);
            }
        }
        float alB0, alB1;
        {
            float mx0 = -1e30f, mx1 = -1e30f;
#pragma unroll
            for (int j = 0; j < 8; j++) {
                mx0 = fmaxf(mx0, fmaxf(s1[j][0], s1[j][1]));
                mx1 = fmaxf(mx1, fmaxf(s1[j][2], s1[j][3]));
            }
            mx0 = fmaxf(mx0, __shfl_xor_sync(0xffffffffu, mx0, 1));
            mx0 = fmaxf(mx0, __shfl_xor_sync(0xffffffffu, mx0, 2));
            mx1 = fmaxf(mx1, __shfl_xor_sync(0xffffffffu, mx1, 1));
            mx1 = fmaxf(mx1, __shfl_xor_sync(0xffffffffu, mx1, 2));
            float mn0 = fmaxf(mpB0, mx0), mn1 = fmaxf(mpB1, mx1);
            alB0 = exp2f(mpB0 - mn0); alB1 = exp2f(mpB1 - mn1);
            mpB0 = mn0; mpB1 = mn1;
#pragma unroll
            for (int j = 0; j < 8; j++) {
                ph1[j][0] = ex2_h2(s1[j][0] - mn0, s1[j][1] - mn0);
                ph1[j][1] = ex2_h2(s1[j][2] - mn1, s1[j][3] - mn1);
            }
        }

#pragma unroll
        for (int j = 0; j < 8; j++) {
            oacc0[j][0] *= alA0; oacc0[j][1] *= alA0;
            oacc0[j][2] *= alA1; oacc0[j][3] *= alA1;
            oacc1[j][0] *= alB0; oacc1[j][1] *= alB0;
            oacc1[j][2] *= alB1; oacc1[j][3] *= alB1;
        }

        float accS0[4] = {0.f, 0.f, 0.f, 0.f};
        float accS1[4] = {0.f, 0.f, 0.f, 0.f};
#pragma unroll
        for (int ks = 0; ks < 4; ks++) {
            uint32_t a00 = ph0[2 * ks][0],     a01 = ph0[2 * ks][1];
            uint32_t a02 = ph0[2 * ks + 1][0], a03 = ph0[2 * ks + 1][1];
            uint32_t a10 = ph1[2 * ks][0],     a11 = ph1[2 * ks][1];
            uint32_t a12 = ph1[2 * ks + 1][0], a13 = ph1[2 * ks + 1][1];
            mma_f16(accS0, a00, a01, a02, a03, ONES_H2, ONES_H2);
            mma_f16(accS1, a10, a11, a12, a13, ONES_H2, ONES_H2);
#pragma unroll
            for (int p = 0; p < 4; p++) {
                uint32_t vf[4];
                ldsm4t(vf, vb + (uint32_t)(ks * 16) * APITCH + p * 32 + aoff);
                mma_f16(oacc0[2 * p],     a00, a01, a02, a03, vf[0], vf[1]);
                mma_f16(oacc0[2 * p + 1], a00, a01, a02, a03, vf[2], vf[3]);
                mma_f16(oacc1[2 * p],     a10, a11, a12, a13, vf[0], vf[1]);
                mma_f16(oacc1[2 * p + 1], a10, a11, a12, a13, vf[2], vf[3]);
            }
        }
        lsA0 = lsA0 * alA0 + accS0[0];
        lsA1 = lsA1 * alA1 + accS0[2];
        lsB0 = lsB0 * alB0 + accS1[0];
        lsB1 = lsB1 * alB1 + accS1[2];

        if (kt + 1 < nt) {
            if (kt + 2 < nt) { CP_WAIT1(); } else { CP_WAIT0(); }
            __syncthreads();
        }
    }

    float iA0 = 1.f / lsA0, iA1 = 1.f / lsA1;
    float iB0 = 1.f / lsB0, iB1 = 1.f / lsB1;

    __half* base0 = g_cth + (size_t)(bS + m0 + wid * 32 + g) * D + h * 64;
    __half* base1 = base0 + (size_t)16 * D;
#pragma unroll
    for (int jn = 0; jn < 8; jn++) {
        int off = jn * 8 + tg * 2;
        *(uint32_t*)(base0 + off) = pack_h2(oacc0[jn][0] * iA0, oacc0[jn][1] * iA0);
        *(uint32_t*)(base0 + (size_t)8 * D + off) =
            pack_h2(oacc0[jn][2] * iA1, oacc0[jn][3] * iA1);
        *(uint32_t*)(base1 + off) = pack_h2(oacc1[jn][0] * iB0, oacc1[jn][1] * iB0);
        *(uint32_t*)(base1 + (size_t)8 * D + off) =
            pack_h2(oacc1[jn][2] * iB1, oacc1[jn][3] * iB1);
    }
}

// ---------------------------------------------------------------------------
extern "C" void kernel_launch(void* const* d_in, const int* in_sizes, int n_in,
                              void* d_out, int out_size)
{
    const float* x  = (const float*)d_in[0];
    const float* Wq = (const float*)d_in[1];
    const float* Wk = (const float*)d_in[2];
    const float* Wv = (const float*)d_in[3];
    const float* Wo = (const float*)d_in[4];
    const float* bo = (const float*)d_in[5];
    float* out = (float*)d_out;

    static bool attr_set = false;
    if (!attr_set) {
        cudaFuncSetAttribute(gemm_mma<0>, cudaFuncAttributeMaxDynamicSharedMemorySize, GSMEM);
        cudaFuncSetAttribute(gemm_mma<1>, cudaFuncAttributeMaxDynamicSharedMemorySize, GSMEM);
        cudaFuncSetAttribute(attn_mma,    cudaFuncAttributeMaxDynamicSharedMemorySize, ASMEM);
        attr_set = true;
    }

    conv_all<<<4096 + (MTOT * D / 4) / 256, 256>>>(x, Wq, Wk, Wv, Wo);
    gemm_mma<0><<<dim3(8, MTOT / 256, 3), 256, GSMEM>>>(nullptr, nullptr);
    attn_mma<<<dim3(SEQ / 128, NHEAD, BATCH), 128, ASMEM>>>();
    gemm_mma<1><<<dim3(8, MTOT / 256, 1), 256, GSMEM>>>(out, bo);
}

// round 16
// speedup vs baseline: 1.0859x; 1.0859x over previous
#include <cuda_runtime.h>
#include <cuda_fp16.h>
#include <cstdint>

#define D      1024
#define NHEAD  16
#define HDIM   64
#define BATCH  4
#define SEQ    2048
#define MTOT   (BATCH*SEQ)   // 8192

// ---------------- scratch (__device__ globals; no allocation allowed) ------
__device__ __half g_xf[(size_t)MTOT * D];          // x as fp16
__device__ __half g_cth[(size_t)MTOT * D];         // ctx as fp16 (attn output)
__device__ __half g_wh[4][(size_t)D * D];          // W^T fp16 [n][k]: 0=q 1=k 2=v 3=o

__device__ __half g_qh[(size_t)MTOT * D];          // Q fp16, scale folded
__device__ __half g_kh[(size_t)MTOT * D];          // K fp16
__device__ __half g_vh[(size_t)MTOT * D];          // V fp16 (row-major [tok][hd])

// ---------------- small helpers --------------------------------------------
__device__ __forceinline__ uint32_t smem_u32(const void* p) {
    return (uint32_t)__cvta_generic_to_shared(p);
}
__device__ __forceinline__ void cp16(uint32_t dst, const void* src) {
    asm volatile("cp.async.cg.shared.global [%0], [%1], 16;" :: "r"(dst), "l"(src) : "memory");
}
#define CP_COMMIT() asm volatile("cp.async.commit_group;" ::: "memory")
#define CP_WAIT0()  asm volatile("cp.async.wait_group 0;" ::: "memory")
#define CP_WAIT1()  asm volatile("cp.async.wait_group 1;" ::: "memory")

__device__ __forceinline__ void ldsm4(uint32_t* r, uint32_t a) {
    asm volatile("ldmatrix.sync.aligned.m8n8.x4.shared.b16 {%0,%1,%2,%3}, [%4];"
        : "=r"(r[0]), "=r"(r[1]), "=r"(r[2]), "=r"(r[3]) : "r"(a));
}
__device__ __forceinline__ void ldsm4t(uint32_t* r, uint32_t a) {
    asm volatile("ldmatrix.sync.aligned.m8n8.x4.trans.shared.b16 {%0,%1,%2,%3}, [%4];"
        : "=r"(r[0]), "=r"(r[1]), "=r"(r[2]), "=r"(r[3]) : "r"(a));
}
// fp32-accumulate MMA
__device__ __forceinline__ void mma_f16(float* c, uint32_t a0, uint32_t a1, uint32_t a2,
                                        uint32_t a3, uint32_t b0, uint32_t b1) {
    asm volatile(
        "mma.sync.aligned.m16n8k16.row.col.f32.f16.f16.f32 "
        "{%0,%1,%2,%3}, {%4,%5,%6,%7}, {%8,%9}, {%0,%1,%2,%3};"
        : "+f"(c[0]), "+f"(c[1]), "+f"(c[2]), "+f"(c[3])
        : "r"(a0), "r"(a1), "r"(a2), "r"(a3), "r"(b0), "r"(b1));
}
// fp16-accumulate MMA (2x rate): c[0] = row g (2 cols packed), c[1] = row g+8
__device__ __forceinline__ void mma_h16(uint32_t* c, uint32_t a0, uint32_t a1, uint32_t a2,
                                        uint32_t a3, uint32_t b0, uint32_t b1) {
    asm volatile(
        "mma.sync.aligned.m16n8k16.row.col.f16.f16.f16.f16 "
        "{%0,%1}, {%2,%3,%4,%5}, {%6,%7}, {%0,%1};"
        : "+r"(c[0]), "+r"(c[1])
        : "r"(a0), "r"(a1), "r"(a2), "r"(a3), "r"(b0), "r"(b1));
}
__device__ __forceinline__ uint32_t pack_h2(float a, float b) {
    __half2 h = __floats2half2_rn(a, b);
    return *reinterpret_cast<uint32_t*>(&h);
}
__device__ __forceinline__ uint32_t h2max(uint32_t a, uint32_t b) {
    __half2 r = __hmax2(*(__half2*)&a, *(__half2*)&b);
    return *(uint32_t*)&r;
}
__device__ __forceinline__ uint32_t h2add(uint32_t a, uint32_t b) {
    __half2 r = __hadd2(*(__half2*)&a, *(__half2*)&b);
    return *(uint32_t*)&r;
}
__device__ __forceinline__ uint32_t h2sub(uint32_t a, uint32_t b) {
    __half2 r = __hsub2(*(__half2*)&a, *(__half2*)&b);
    return *(uint32_t*)&r;
}
__device__ __forceinline__ uint32_t ex2p(uint32_t r) {
    asm("ex2.approx.f16x2 %0, %0;" : "+r"(r));
    return r;
}
__device__ __forceinline__ float h2max_f(uint32_t a) {
    __half2 h = *(__half2*)&a;
    return fmaxf(__low2float(h), __high2float(h));
}

#define MASK_LO 0x0000F800u   // -32768 in low half
#define MASK_HI 0xF8000000u   // -32768 in high half

// ---------------- fused conversions (one launch) ----------------------------
__global__ void __launch_bounds__(256) conv_all(const float* __restrict__ x,
                                                const float* __restrict__ Wq,
                                                const float* __restrict__ Wk,
                                                const float* __restrict__ Wv,
                                                const float* __restrict__ Wo)
{
    int bid = blockIdx.x;
    if (bid < 4096) {
        int zW = bid >> 10;
        int yW = (bid >> 5) & 31;
        int xW = bid & 31;
        const float* W = (zW == 0) ? Wq : (zW == 1) ? Wk : (zW == 2) ? Wv : Wo;
        __half* th = g_wh[zW];

        __shared__ float t[32][33];
        int n0 = xW * 32, k0 = yW * 32;
        int tx = threadIdx.x & 31, ty = threadIdx.x >> 5;
#pragma unroll
        for (int i = 0; i < 4; i++)
            t[ty + i * 8][tx] = W[(size_t)(k0 + ty + i * 8) * D + n0 + tx];
        __syncthreads();
#pragma unroll
        for (int i = 0; i < 4; i++)
            th[(size_t)(n0 + ty + i * 8) * D + k0 + tx] = __float2half(t[tx][ty + i * 8]);
    } else {
        int i = (bid - 4096) * 256 + threadIdx.x;
        float4 v = ((const float4*)x)[i];
        uint2 o;
        o.x = pack_h2(v.x, v.y);
        o.y = pack_h2(v.z, v.w);
        ((uint2*)g_xf)[i] = o;
    }
}

// ---------------- mma.sync fp16 GEMM (round-12 exact: 2-stage, BK=64) -------
#define GTILE_B  (128 * 128)             // 16384 (128 rows x 128 bytes)
#define GSTG_B   (2 * GTILE_B)           // 32768 (A tile + W tile)
#define GSMEM    (2 * GSTG_B)            // 65536 (double buffered)

#define QSCALE (0.125f * 1.4426950408889634f)

template<int MODE>   // 0 = QKV (blockIdx.z picks), 1 = out-proj
__global__ void __launch_bounds__(256, 2) gemm_mma(float* __restrict__ outp,
                                                   const float* __restrict__ bias)
{
    extern __shared__ char sm[];
    const uint32_t smb = smem_u32(sm);
    const int tid = threadIdx.x;
    const int wid = tid >> 5, lane = tid & 31;
    const int g = lane >> 2, tg = lane & 3;
    const int wm = wid & 3, wn = wid >> 2;
    const int n0 = blockIdx.x * 128, m0 = blockIdx.y * 128;
    const int z = (MODE == 0) ? blockIdx.z : 3;

    const int am  = (lane & 7) + ((lane >> 3) & 1) * 8;
    const int akh = ((lane >> 4) & 1) * 16;
    const int bn  = (lane & 7) + ((lane >> 4) & 1) * 8;
    const int bkh = ((lane >> 3) & 1) * 16;
    const uint32_t kxorA = (uint32_t)(am & 7) << 4;
    const uint32_t kxorB = (uint32_t)(bn & 7) << 4;

    uint32_t koa[4], kob[4];
#pragma unroll
    for (int ks = 0; ks < 4; ks++) {
        koa[ks] = (uint32_t)(ks * 32 + akh) ^ kxorA;
        kob[ks] = (uint32_t)(ks * 32 + bkh) ^ kxorB;
    }

    const __half* srcb[2] = {
        ((MODE == 0) ? g_xf : g_cth) + (size_t)m0 * D,
        g_wh[z] + (size_t)n0 * D };

    auto load_stage = [&](int kb, int st) {
#pragma unroll
        for (int i = 0; i < 8; i++) {
            int idx = tid + i * 256;
            int t   = idx >> 10;
            int rid = (idx >> 3) & 127;
            int c   = idx & 7;
            uint32_t dst = smb + st * GSTG_B + t * GTILE_B + rid * 128
                         + ((uint32_t)(c * 16) ^ ((uint32_t)(rid & 7) << 4));
            cp16(dst, srcb[t] + (size_t)rid * D + kb * 64 + c * 8);
        }
    };

    float acc[2][8][4];
#pragma unroll
    for (int i = 0; i < 2; i++)
#pragma unroll
        for (int j = 0; j < 8; j++)
#pragma unroll
            for (int c = 0; c < 4; c++) acc[i][j][c] = 0.f;

    load_stage(0, 0); CP_COMMIT();

    for (int kb = 0; kb < 16; kb++) {
        const int st = kb & 1;
        if (kb + 1 < 16) { load_stage(kb + 1, st ^ 1); CP_COMMIT(); CP_WAIT1(); }
        else             { CP_WAIT0(); }
        __syncthreads();

        const uint32_t sa = smb + st * GSTG_B + (uint32_t)(wm * 32 + am) * 128;
        const uint32_t sb = smb + st * GSTG_B + GTILE_B + (uint32_t)(wn * 64 + bn) * 128;

#pragma unroll
        for (int ks = 0; ks < 4; ks++) {
            uint32_t aF[2][4];
#pragma unroll
            for (int i = 0; i < 2; i++)
                ldsm4(aF[i], sa + (uint32_t)(i * 16) * 128 + koa[ks]);
#pragma unroll
            for (int p = 0; p < 4; p++) {
                uint32_t bF[4];
                ldsm4(bF, sb + (uint32_t)(p * 16) * 128 + kob[ks]);
#pragma unroll
                for (int i = 0; i < 2; i++) {
                    mma_f16(acc[i][2 * p],     aF[i][0], aF[i][1], aF[i][2], aF[i][3], bF[0], bF[1]);
                    mma_f16(acc[i][2 * p + 1], aF[i][0], aF[i][1], aF[i][2], aF[i][3], bF[2], bF[3]);
                }
            }
        }
        __syncthreads();
    }

#pragma unroll
    for (int i = 0; i < 2; i++) {
#pragma unroll
        for (int j = 0; j < 8; j++) {
            int row = m0 + wm * 32 + i * 16 + g;
            int col = n0 + wn * 64 + j * 8 + tg * 2;
            float v0 = acc[i][j][0], v1 = acc[i][j][1];
            float v2 = acc[i][j][2], v3 = acc[i][j][3];
            if (MODE == 0) {
                if (z == 0) {
                    v0 *= QSCALE; v1 *= QSCALE; v2 *= QSCALE; v3 *= QSCALE;
                    *(uint32_t*)&g_qh[(size_t)row * D + col]       = pack_h2(v0, v1);
                    *(uint32_t*)&g_qh[(size_t)(row + 8) * D + col] = pack_h2(v2, v3);
                } else if (z == 1) {
                    *(uint32_t*)&g_kh[(size_t)row * D + col]       = pack_h2(v0, v1);
                    *(uint32_t*)&g_kh[(size_t)(row + 8) * D + col] = pack_h2(v2, v3);
                } else {
                    *(uint32_t*)&g_vh[(size_t)row * D + col]       = pack_h2(v0, v1);
                    *(uint32_t*)&g_vh[(size_t)(row + 8) * D + col] = pack_h2(v2, v3);
                }
            } else {
                float b0 = bias[col], b1 = bias[col + 1];
                *(float2*)&outp[(size_t)row * D + col]       = make_float2(v0 + b0, v1 + b1);
                *(float2*)&outp[(size_t)(row + 8) * D + col] = make_float2(v2 + b0, v3 + b1);
            }
        }
    }
}

// ---------------- FlashAttention-2: fp16-accum QK^T, packed softmax ---------
#define APITCH  144
#define AQ_B    (128 * APITCH)          // 18432
#define AKV_B   (64 * APITCH)           // 9216
#define ASTAGE  (2 * AKV_B)             // 18432
#define ASMEM   (AQ_B + 3 * ASTAGE)     // 73728 (Q + 3-stage ring)
#define ONES_H2 0x3C003C00u

__global__ void __launch_bounds__(128, 2) attn_mma()
{
    extern __shared__ char sm[];
    const uint32_t smb = smem_u32(sm);
    const int tid = threadIdx.x, wid = tid >> 5, lane = tid & 31;
    const int g = lane >> 2, tg = lane & 3;
    const int mb = gridDim.x - 1 - blockIdx.x;   // heavy CTAs first
    const int h = blockIdx.y, b = blockIdx.z;
    const int m0 = mb * 128, bS = b * SEQ;
    const int nt = 2 * mb + 2;

    const uint32_t aoff = (uint32_t)((lane & 7) + ((lane >> 3) & 1) * 8) * APITCH
                        + ((lane >> 4) & 1) * 16;
    const uint32_t boff = (uint32_t)((lane & 7) + ((lane >> 4) & 1) * 8) * APITCH
                        + ((lane >> 3) & 1) * 16;

    const __half* Qg = g_qh + (size_t)(bS + m0) * D + h * 64;
    const __half* Kg = g_kh + (size_t)bS * D + h * 64;
    const __half* Vg = g_vh + (size_t)bS * D + h * 64;

    auto load_tile = [&](int kt, int st) {
        int n0 = kt * 64;
#pragma unroll
        for (int i = 0; i < 4; i++) {
            int idx = tid + i * 128;
            int rid = idx >> 3, c = idx & 7;
            cp16(smb + AQ_B + st * ASTAGE + rid * APITCH + c * 16,
                 Kg + (size_t)(n0 + rid) * D + c * 8);
            cp16(smb + AQ_B + st * ASTAGE + AKV_B + rid * APITCH + c * 16,
                 Vg + (size_t)(n0 + rid) * D + c * 8);
        }
    };

#pragma unroll
    for (int i = 0; i < 8; i++) {
        int idx = tid + i * 128;
        int rid = idx >> 3, c = idx & 7;
        cp16(smb + rid * APITCH + c * 16, Qg + (size_t)rid * D + c * 8);
    }
    load_tile(0, 0); CP_COMMIT();      // group0 = Q + tile0
    load_tile(1, 1); CP_COMMIT();      // group1 = tile1
    CP_WAIT1();                        // Q + tile0 ready
    __syncthreads();

    uint32_t qf0[4][4], qf1[4][4];
    {
        uint32_t q0 = smb + (uint32_t)(wid * 32) * APITCH + aoff;
        uint32_t q1 = q0 + 16 * APITCH;
#pragma unroll
        for (int ks = 0; ks < 4; ks++) {
            ldsm4(qf0[ks], q0 + ks * 32);
            ldsm4(qf1[ks], q1 + ks * 32);
        }
    }

    float oacc0[8][4], oacc1[8][4];
#pragma unroll
    for (int j = 0; j < 8; j++)
#pragma unroll
        for (int c = 0; c < 4; c++) { oacc0[j][c] = 0.f; oacc1[j][c] = 0.f; }
    float mpA0 = -1e30f, mpA1 = -1e30f, mpB0 = -1e30f, mpB1 = -1e30f;
    float lsA0 = 0.f, lsA1 = 0.f, lsB0 = 0.f, lsB1 = 0.f;

    const int rA0 = m0 + wid * 32 + g;
    const int rA1 = rA0 + 8;
    const int rB0 = rA0 + 16;
    const int rB1 = rA0 + 24;

    for (int kt = 0; kt < nt; kt++) {
        if (kt + 2 < nt) { load_tile(kt + 2, (kt + 2) % 3); CP_COMMIT(); }

        const uint32_t kb = smb + AQ_B + (uint32_t)(kt % 3) * ASTAGE;
        const uint32_t vb = kb + AKV_B;

        // S = Q @ K^T, fp16 accumulators (packed: [j][0]=row g, [j][1]=row g+8)
        uint32_t sp0[8][2], sp1[8][2];
#pragma unroll
        for (int j = 0; j < 8; j++) {
            sp0[j][0] = 0; sp0[j][1] = 0;
            sp1[j][0] = 0; sp1[j][1] = 0;
        }

#pragma unroll
        for (int ks = 0; ks < 4; ks++) {
#pragma unroll
            for (int p = 0; p < 4; p++) {
                uint32_t kf[4];
                ldsm4(kf, kb + (uint32_t)(p * 16) * APITCH + ks * 32 + boff);
                mma_h16(sp0[2 * p],     qf0[ks][0], qf0[ks][1], qf0[ks][2], qf0[ks][3], kf[0], kf[1]);
                mma_h16(sp0[2 * p + 1], qf0[ks][0], qf0[ks][1], qf0[ks][2], qf0[ks][3], kf[2], kf[3]);
                mma_h16(sp1[2 * p],     qf1[ks][0], qf1[ks][1], qf1[ks][2], qf1[ks][3], kf[0], kf[1]);
                mma_h16(sp1[2 * p + 1], qf1[ks][0], qf1[ks][1], qf1[ks][2], qf1[ks][3], kf[2], kf[3]);
            }
        }

        // causal mask: add -32768 to masked lanes (packed)
        const int n0k = kt * 64;
        if (n0k + 63 > rA0) {
#pragma unroll
            for (int j = 0; j < 8; j++) {
                int c0 = n0k + j * 8 + tg * 2;
                uint32_t m0m = ((c0 > rA0) ? MASK_LO : 0u) | ((c0 + 1 > rA0) ? MASK_HI : 0u);
                uint32_t m1m = ((c0 > rA1) ? MASK_LO : 0u) | ((c0 + 1 > rA1) ? MASK_HI : 0u);
                if (m0m) sp0[j][0] = h2add(sp0[j][0], m0m);
                if (m1m) sp0[j][1] = h2add(sp0[j][1], m1m);
            }
        }
        if (n0k + 63 > rB0) {
#pragma unroll
            for (int j = 0; j < 8; j++) {
                int c0 = n0k + j * 8 + tg * 2;
                uint32_t m0m = ((c0 > rB0) ? MASK_LO : 0u) | ((c0 + 1 > rB0) ? MASK_HI : 0u);
                uint32_t m1m = ((c0 > rB1) ? MASK_LO : 0u) | ((c0 + 1 > rB1) ? MASK_HI : 0u);
                if (m0m) sp1[j][0] = h2add(sp1[j][0], m0m);
                if (m1m) sp1[j][1] = h2add(sp1[j][1], m1m);
            }
        }

        // softmax half 0 (packed)
        uint32_t ph0[8][2], ph1[8][2];
        float alA0, alA1;
        {
            uint32_t v0 = sp0[0][0], v1 = sp0[0][1];
#pragma unroll
            for (int j = 1; j < 8; j++) {
                v0 = h2max(v0, sp0[j][0]);
                v1 = h2max(v1, sp0[j][1]);
            }
            float mx0 = h2max_f(v0), mx1 = h2max_f(v1);
            mx0 = fmaxf(mx0, __shfl_xor_sync(0xffffffffu, mx0, 1));
            mx0 = fmaxf(mx0, __shfl_xor_sync(0xffffffffu, mx0, 2));
            mx1 = fmaxf(mx1, __shfl_xor_sync(0xffffffffu, mx1, 1));
            mx1 = fmaxf(mx1, __shfl_xor_sync(0xffffffffu, mx1, 2));
            float mn0 = fmaxf(mpA0, mx0), mn1 = fmaxf(mpA1, mx1);
            alA0 = exp2f(mpA0 - mn0); alA1 = exp2f(mpA1 - mn1);
            mpA0 = mn0; mpA1 = mn1;
            uint32_t hm0 = pack_h2(mn0, mn0), hm1 = pack_h2(mn1, mn1);
#pragma unroll
            for (int j = 0; j < 8; j++) {
                ph0[j][0] = ex2p(h2sub(sp0[j][0], hm0));
                ph0[j][1] = ex2p(h2sub(sp0[j][1], hm1));
            }
        }
        // softmax half 1 (packed)
        float alB0, alB1;
        {
            uint32_t v0 = sp1[0][0], v1 = sp1[0][1];
#pragma unroll
            for (int j = 1; j < 8; j++) {
                v0 = h2max(v0, sp1[j][0]);
                v1 = h2max(v1, sp1[j][1]);
            }
            float mx0 = h2max_f(v0), mx1 = h2max_f(v1);
            mx0 = fmaxf(mx0, __shfl_xor_sync(0xffffffffu, mx0, 1));
            mx0 = fmaxf(mx0, __shfl_xor_sync(0xffffffffu, mx0, 2));
            mx1 = fmaxf(mx1, __shfl_xor_sync(0xffffffffu, mx1, 1));
            mx1 = fmaxf(mx1, __shfl_xor_sync(0xffffffffu, mx1, 2));
            float mn0 = fmaxf(mpB0, mx0), mn1 = fmaxf(mpB1, mx1);
            alB0 = exp2f(mpB0 - mn0); alB1 = exp2f(mpB1 - mn1);
            mpB0 = mn0; mpB1 = mn1;
            uint32_t hm0 = pack_h2(mn0, mn0), hm1 = pack_h2(mn1, mn1);
#pragma unroll
            for (int j = 0; j < 8; j++) {
                ph1[j][0] = ex2p(h2sub(sp1[j][0], hm0));
                ph1[j][1] = ex2p(h2sub(sp1[j][1], hm1));
            }
        }

        // rescale O
#pragma unroll
        for (int j = 0; j < 8; j++) {
            oacc0[j][0] *= alA0; oacc0[j][1] *= alA0;
            oacc0[j][2] *= alA1; oacc0[j][3] *= alA1;
            oacc1[j][0] *= alB0; oacc1[j][1] *= alB0;
            oacc1[j][2] *= alB1; oacc1[j][3] *= alB1;
        }

        // O += P @ V (fp32 acc) ; row-sums via ones-MMA
        float accS0[4] = {0.f, 0.f, 0.f, 0.f};
        float accS1[4] = {0.f, 0.f, 0.f, 0.f};
#pragma unroll
        for (int ks = 0; ks < 4; ks++) {
            uint32_t a00 = ph0[2 * ks][0],     a01 = ph0[2 * ks][1];
            uint32_t a02 = ph0[2 * ks + 1][0], a03 = ph0[2 * ks + 1][1];
            uint32_t a10 = ph1[2 * ks][0],     a11 = ph1[2 * ks][1];
            uint32_t a12 = ph1[2 * ks + 1][0], a13 = ph1[2 * ks + 1][1];
            mma_f16(accS0, a00, a01, a02, a03, ONES_H2, ONES_H2);
            mma_f16(accS1, a10, a11, a12, a13, ONES_H2, ONES_H2);
#pragma unroll
            for (int p = 0; p < 4; p++) {
                uint32_t vf[4];
                ldsm4t(vf, vb + (uint32_t)(ks * 16) * APITCH + p * 32 + aoff);
                mma_f16(oacc0[2 * p],     a00, a01, a02, a03, vf[0], vf[1]);
                mma_f16(oacc0[2 * p + 1], a00, a01, a02, a03, vf[2], vf[3]);
                mma_f16(oacc1[2 * p],     a10, a11, a12, a13, vf[0], vf[1]);
                mma_f16(oacc1[2 * p + 1], a10, a11, a12, a13, vf[2], vf[3]);
            }
        }
        lsA0 = lsA0 * alA0 + accS0[0];
        lsA1 = lsA1 * alA1 + accS0[2];
        lsB0 = lsB0 * alB0 + accS1[0];
        lsB1 = lsB1 * alB1 + accS1[2];

        if (kt + 1 < nt) {
            if (kt + 2 < nt) { CP_WAIT1(); } else { CP_WAIT0(); }
            __syncthreads();
        }
    }

    float iA0 = 1.f / lsA0, iA1 = 1.f / lsA1;
    float iB0 = 1.f / lsB0, iB1 = 1.f / lsB1;

    __half* base0 = g_cth + (size_t)(bS + m0 + wid * 32 + g) * D + h * 64;
    __half* base1 = base0 + (size_t)16 * D;
#pragma unroll
    for (int jn = 0; jn < 8; jn++) {
        int off = jn * 8 + tg * 2;
        *(uint32_t*)(base0 + off) = pack_h2(oacc0[jn][0] * iA0, oacc0[jn][1] * iA0);
        *(uint32_t*)(base0 + (size_t)8 * D + off) =
            pack_h2(oacc0[jn][2] * iA1, oacc0[jn][3] * iA1);
        *(uint32_t*)(base1 + off) = pack_h2(oacc1[jn][0] * iB0, oacc1[jn][1] * iB0);
        *(uint32_t*)(base1 + (size_t)8 * D + off) =
            pack_h2(oacc1[jn][2] * iB1, oacc1[jn][3] * iB1);
    }
}

// ---------------------------------------------------------------------------
extern "C" void kernel_launch(void* const* d_in, const int* in_sizes, int n_in,
                              void* d_out, int out_size)
{
    const float* x  = (const float*)d_in[0];
    const float* Wq = (const float*)d_in[1];
    const float* Wk = (const float*)d_in[2];
    const float* Wv = (const float*)d_in[3];
    const float* Wo = (const float*)d_in[4];
    const float* bo = (const float*)d_in[5];
    float* out = (float*)d_out;

    static bool attr_set = false;
    if (!attr_set) {
        cudaFuncSetAttribute(gemm_mma<0>, cudaFuncAttributeMaxDynamicSharedMemorySize, GSMEM);
        cudaFuncSetAttribute(gemm_mma<1>, cudaFuncAttributeMaxDynamicSharedMemorySize, GSMEM);
        cudaFuncSetAttribute(attn_mma,    cudaFuncAttributeMaxDynamicSharedMemorySize, ASMEM);
        attr_set = true;
    }

    conv_all<<<4096 + (MTOT * D / 4) / 256, 256>>>(x, Wq, Wk, Wv, Wo);
    gemm_mma<0><<<dim3(8, 64, 3), 256, GSMEM>>>(nullptr, nullptr);
    attn_mma<<<dim3(SEQ / 128, NHEAD, BATCH), 128, ASMEM>>>();
    gemm_mma<1><<<dim3(8, 64, 1), 256, GSMEM>>>(out, bo);
}

// round 17
// speedup vs baseline: 1.0876x; 1.0015x over previous
#include <cuda_runtime.h>
#include <cuda_fp16.h>
#include <cstdint>

#define D      1024
#define NHEAD  16
#define HDIM   64
#define BATCH  4
#define SEQ    2048
#define MTOT   (BATCH*SEQ)   // 8192

// ---------------- scratch (__device__ globals; no allocation allowed) ------
__device__ __half g_xf[(size_t)MTOT * D];          // x as fp16
__device__ __half g_cth[(size_t)MTOT * D];         // ctx as fp16 (attn output)
__device__ __half g_wh[4][(size_t)D * D];          // W^T fp16 [n][k]: 0=q 1=k 2=v 3=o

__device__ __half g_qh[(size_t)MTOT * D];          // Q fp16, scale folded
__device__ __half g_kh[(size_t)MTOT * D];          // K fp16
__device__ __half g_vh[(size_t)MTOT * D];          // V fp16 (row-major [tok][hd])

// ---------------- small helpers --------------------------------------------
__device__ __forceinline__ uint32_t smem_u32(const void* p) {
    return (uint32_t)__cvta_generic_to_shared(p);
}
__device__ __forceinline__ void cp16(uint32_t dst, const void* src) {
    asm volatile("cp.async.cg.shared.global [%0], [%1], 16;" :: "r"(dst), "l"(src) : "memory");
}
#define CP_COMMIT() asm volatile("cp.async.commit_group;" ::: "memory")
#define CP_WAIT0()  asm volatile("cp.async.wait_group 0;" ::: "memory")
#define CP_WAIT1()  asm volatile("cp.async.wait_group 1;" ::: "memory")

__device__ __forceinline__ void ldsm4(uint32_t* r, uint32_t a) {
    asm volatile("ldmatrix.sync.aligned.m8n8.x4.shared.b16 {%0,%1,%2,%3}, [%4];"
        : "=r"(r[0]), "=r"(r[1]), "=r"(r[2]), "=r"(r[3]) : "r"(a));
}
__device__ __forceinline__ void ldsm4t(uint32_t* r, uint32_t a) {
    asm volatile("ldmatrix.sync.aligned.m8n8.x4.trans.shared.b16 {%0,%1,%2,%3}, [%4];"
        : "=r"(r[0]), "=r"(r[1]), "=r"(r[2]), "=r"(r[3]) : "r"(a));
}
// fp32-accumulate MMA
__device__ __forceinline__ void mma_f16(float* c, uint32_t a0, uint32_t a1, uint32_t a2,
                                        uint32_t a3, uint32_t b0, uint32_t b1) {
    asm volatile(
        "mma.sync.aligned.m16n8k16.row.col.f32.f16.f16.f32 "
        "{%0,%1,%2,%3}, {%4,%5,%6,%7}, {%8,%9}, {%0,%1,%2,%3};"
        : "+f"(c[0]), "+f"(c[1]), "+f"(c[2]), "+f"(c[3])
        : "r"(a0), "r"(a1), "r"(a2), "r"(a3), "r"(b0), "r"(b1));
}
// fp16-accumulate MMA (2x rate): c[0] = row g (2 cols packed), c[1] = row g+8
__device__ __forceinline__ void mma_h16(uint32_t* c, uint32_t a0, uint32_t a1, uint32_t a2,
                                        uint32_t a3, uint32_t b0, uint32_t b1) {
    asm volatile(
        "mma.sync.aligned.m16n8k16.row.col.f16.f16.f16.f16 "
        "{%0,%1}, {%2,%3,%4,%5}, {%6,%7}, {%0,%1};"
        : "+r"(c[0]), "+r"(c[1])
        : "r"(a0), "r"(a1), "r"(a2), "r"(a3), "r"(b0), "r"(b1));
}
__device__ __forceinline__ uint32_t pack_h2(float a, float b) {
    __half2 h = __floats2half2_rn(a, b);
    return *reinterpret_cast<uint32_t*>(&h);
}
__device__ __forceinline__ uint32_t h2max(uint32_t a, uint32_t b) {
    __half2 r = __hmax2(*(__half2*)&a, *(__half2*)&b);
    return *(uint32_t*)&r;
}
__device__ __forceinline__ uint32_t h2add(uint32_t a, uint32_t b) {
    __half2 r = __hadd2(*(__half2*)&a, *(__half2*)&b);
    return *(uint32_t*)&r;
}
__device__ __forceinline__ uint32_t h2sub(uint32_t a, uint32_t b) {
    __half2 r = __hsub2(*(__half2*)&a, *(__half2*)&b);
    return *(uint32_t*)&r;
}
__device__ __forceinline__ uint32_t ex2p(uint32_t r) {
    asm("ex2.approx.f16x2 %0, %0;" : "+r"(r));
    return r;
}
__device__ __forceinline__ float h2max_f(uint32_t a) {
    __half2 h = *(__half2*)&a;
    return fmaxf(__low2float(h), __high2float(h));
}

#define MASK_LO 0x0000F800u   // -32768 in low half
#define MASK_HI 0xF8000000u   // -32768 in high half

// ---------------- fused conversions (one launch) ----------------------------
__global__ void __launch_bounds__(256) conv_all(const float* __restrict__ x,
                                                const float* __restrict__ Wq,
                                                const float* __restrict__ Wk,
                                                const float* __restrict__ Wv,
                                                const float* __restrict__ Wo)
{
    int bid = blockIdx.x;
    if (bid < 4096) {
        int zW = bid >> 10;
        int yW = (bid >> 5) & 31;
        int xW = bid & 31;
        const float* W = (zW == 0) ? Wq : (zW == 1) ? Wk : (zW == 2) ? Wv : Wo;
        __half* th = g_wh[zW];

        __shared__ float t[32][33];
        int n0 = xW * 32, k0 = yW * 32;
        int tx = threadIdx.x & 31, ty = threadIdx.x >> 5;
#pragma unroll
        for (int i = 0; i < 4; i++)
            t[ty + i * 8][tx] = W[(size_t)(k0 + ty + i * 8) * D + n0 + tx];
        __syncthreads();
#pragma unroll
        for (int i = 0; i < 4; i++)
            th[(size_t)(n0 + ty + i * 8) * D + k0 + tx] = __float2half(t[tx][ty + i * 8]);
    } else {
        int i = (bid - 4096) * 256 + threadIdx.x;
        float4 v = ((const float4*)x)[i];
        uint2 o;
        o.x = pack_h2(v.x, v.y);
        o.y = pack_h2(v.z, v.w);
        ((uint2*)g_xf)[i] = o;
    }
}

// ---------------- mma.sync fp16 GEMM (round-16 exact: 2-stage, BK=64) -------
#define GTILE_B  (128 * 128)             // 16384 (128 rows x 128 bytes)
#define GSTG_B   (2 * GTILE_B)           // 32768 (A tile + W tile)
#define GSMEM    (2 * GSTG_B)            // 65536 (double buffered)

#define QSCALE (0.125f * 1.4426950408889634f)

template<int MODE>   // 0 = QKV (blockIdx.z picks), 1 = out-proj
__global__ void __launch_bounds__(256, 2) gemm_mma(float* __restrict__ outp,
                                                   const float* __restrict__ bias)
{
    extern __shared__ char sm[];
    const uint32_t smb = smem_u32(sm);
    const int tid = threadIdx.x;
    const int wid = tid >> 5, lane = tid & 31;
    const int g = lane >> 2, tg = lane & 3;
    const int wm = wid & 3, wn = wid >> 2;
    const int n0 = blockIdx.x * 128, m0 = blockIdx.y * 128;
    const int z = (MODE == 0) ? blockIdx.z : 3;

    const int am  = (lane & 7) + ((lane >> 3) & 1) * 8;
    const int akh = ((lane >> 4) & 1) * 16;
    const int bn  = (lane & 7) + ((lane >> 4) & 1) * 8;
    const int bkh = ((lane >> 3) & 1) * 16;
    const uint32_t kxorA = (uint32_t)(am & 7) << 4;
    const uint32_t kxorB = (uint32_t)(bn & 7) << 4;

    uint32_t koa[4], kob[4];
#pragma unroll
    for (int ks = 0; ks < 4; ks++) {
        koa[ks] = (uint32_t)(ks * 32 + akh) ^ kxorA;
        kob[ks] = (uint32_t)(ks * 32 + bkh) ^ kxorB;
    }

    const __half* srcb[2] = {
        ((MODE == 0) ? g_xf : g_cth) + (size_t)m0 * D,
        g_wh[z] + (size_t)n0 * D };

    auto load_stage = [&](int kb, int st) {
#pragma unroll
        for (int i = 0; i < 8; i++) {
            int idx = tid + i * 256;
            int t   = idx >> 10;
            int rid = (idx >> 3) & 127;
            int c   = idx & 7;
            uint32_t dst = smb + st * GSTG_B + t * GTILE_B + rid * 128
                         + ((uint32_t)(c * 16) ^ ((uint32_t)(rid & 7) << 4));
            cp16(dst, srcb[t] + (size_t)rid * D + kb * 64 + c * 8);
        }
    };

    float acc[2][8][4];
#pragma unroll
    for (int i = 0; i < 2; i++)
#pragma unroll
        for (int j = 0; j < 8; j++)
#pragma unroll
            for (int c = 0; c < 4; c++) acc[i][j][c] = 0.f;

    load_stage(0, 0); CP_COMMIT();

    for (int kb = 0; kb < 16; kb++) {
        const int st = kb & 1;
        if (kb + 1 < 16) { load_stage(kb + 1, st ^ 1); CP_COMMIT(); CP_WAIT1(); }
        else             { CP_WAIT0(); }
        __syncthreads();

        const uint32_t sa = smb + st * GSTG_B + (uint32_t)(wm * 32 + am) * 128;
        const uint32_t sb = smb + st * GSTG_B + GTILE_B + (uint32_t)(wn * 64 + bn) * 128;

#pragma unroll
        for (int ks = 0; ks < 4; ks++) {
            uint32_t aF[2][4];
#pragma unroll
            for (int i = 0; i < 2; i++)
                ldsm4(aF[i], sa + (uint32_t)(i * 16) * 128 + koa[ks]);
#pragma unroll
            for (int p = 0; p < 4; p++) {
                uint32_t bF[4];
                ldsm4(bF, sb + (uint32_t)(p * 16) * 128 + kob[ks]);
#pragma unroll
                for (int i = 0; i < 2; i++) {
                    mma_f16(acc[i][2 * p],     aF[i][0], aF[i][1], aF[i][2], aF[i][3], bF[0], bF[1]);
                    mma_f16(acc[i][2 * p + 1], aF[i][0], aF[i][1], aF[i][2], aF[i][3], bF[2], bF[3]);
                }
            }
        }
        __syncthreads();
    }

#pragma unroll
    for (int i = 0; i < 2; i++) {
#pragma unroll
        for (int j = 0; j < 8; j++) {
            int row = m0 + wm * 32 + i * 16 + g;
            int col = n0 + wn * 64 + j * 8 + tg * 2;
            float v0 = acc[i][j][0], v1 = acc[i][j][1];
            float v2 = acc[i][j][2], v3 = acc[i][j][3];
            if (MODE == 0) {
                if (z == 0) {
                    v0 *= QSCALE; v1 *= QSCALE; v2 *= QSCALE; v3 *= QSCALE;
                    *(uint32_t*)&g_qh[(size_t)row * D + col]       = pack_h2(v0, v1);
                    *(uint32_t*)&g_qh[(size_t)(row + 8) * D + col] = pack_h2(v2, v3);
                } else if (z == 1) {
                    *(uint32_t*)&g_kh[(size_t)row * D + col]       = pack_h2(v0, v1);
                    *(uint32_t*)&g_kh[(size_t)(row + 8) * D + col] = pack_h2(v2, v3);
                } else {
                    *(uint32_t*)&g_vh[(size_t)row * D + col]       = pack_h2(v0, v1);
                    *(uint32_t*)&g_vh[(size_t)(row + 8) * D + col] = pack_h2(v2, v3);
                }
            } else {
                float b0 = bias[col], b1 = bias[col + 1];
                *(float2*)&outp[(size_t)row * D + col]       = make_float2(v0 + b0, v1 + b1);
                *(float2*)&outp[(size_t)(row + 8) * D + col] = make_float2(v2 + b0, v3 + b1);
            }
        }
    }
}

// ---------------- FlashAttention-2: fp16-acc QK + interleaved softmax/PV ----
#define APITCH  144
#define AQ_B    (128 * APITCH)          // 18432
#define AKV_B   (64 * APITCH)           // 9216
#define ASTAGE  (2 * AKV_B)             // 18432
#define ASMEM   (AQ_B + 3 * ASTAGE)     // 73728 (Q + 3-stage ring)
#define ONES_H2 0x3C003C00u

__global__ void __launch_bounds__(128, 2) attn_mma()
{
    extern __shared__ char sm[];
    const uint32_t smb = smem_u32(sm);
    const int tid = threadIdx.x, wid = tid >> 5, lane = tid & 31;
    const int g = lane >> 2, tg = lane & 3;
    const int mb = gridDim.x - 1 - blockIdx.x;   // heavy CTAs first
    const int h = blockIdx.y, b = blockIdx.z;
    const int m0 = mb * 128, bS = b * SEQ;
    const int nt = 2 * mb + 2;

    const uint32_t aoff = (uint32_t)((lane & 7) + ((lane >> 3) & 1) * 8) * APITCH
                        + ((lane >> 4) & 1) * 16;
    const uint32_t boff = (uint32_t)((lane & 7) + ((lane >> 4) & 1) * 8) * APITCH
                        + ((lane >> 3) & 1) * 16;

    const __half* Qg = g_qh + (size_t)(bS + m0) * D + h * 64;
    const __half* Kg = g_kh + (size_t)bS * D + h * 64;
    const __half* Vg = g_vh + (size_t)bS * D + h * 64;

    auto load_tile = [&](int kt, int st) {
        int n0 = kt * 64;
#pragma unroll
        for (int i = 0; i < 4; i++) {
            int idx = tid + i * 128;
            int rid = idx >> 3, c = idx & 7;
            cp16(smb + AQ_B + st * ASTAGE + rid * APITCH + c * 16,
                 Kg + (size_t)(n0 + rid) * D + c * 8);
            cp16(smb + AQ_B + st * ASTAGE + AKV_B + rid * APITCH + c * 16,
                 Vg + (size_t)(n0 + rid) * D + c * 8);
        }
    };

#pragma unroll
    for (int i = 0; i < 8; i++) {
        int idx = tid + i * 128;
        int rid = idx >> 3, c = idx & 7;
        cp16(smb + rid * APITCH + c * 16, Qg + (size_t)rid * D + c * 8);
    }
    load_tile(0, 0); CP_COMMIT();      // group0 = Q + tile0
    load_tile(1, 1); CP_COMMIT();      // group1 = tile1
    CP_WAIT1();                        // Q + tile0 ready
    __syncthreads();

    uint32_t qf0[4][4], qf1[4][4];
    {
        uint32_t q0 = smb + (uint32_t)(wid * 32) * APITCH + aoff;
        uint32_t q1 = q0 + 16 * APITCH;
#pragma unroll
        for (int ks = 0; ks < 4; ks++) {
            ldsm4(qf0[ks], q0 + ks * 32);
            ldsm4(qf1[ks], q1 + ks * 32);
        }
    }

    float oacc0[8][4], oacc1[8][4];
#pragma unroll
    for (int j = 0; j < 8; j++)
#pragma unroll
        for (int c = 0; c < 4; c++) { oacc0[j][c] = 0.f; oacc1[j][c] = 0.f; }
    float mpA0 = -1e30f, mpA1 = -1e30f, mpB0 = -1e30f, mpB1 = -1e30f;
    float lsA0 = 0.f, lsA1 = 0.f, lsB0 = 0.f, lsB1 = 0.f;

    const int rA0 = m0 + wid * 32 + g;
    const int rA1 = rA0 + 8;
    const int rB0 = rA0 + 16;
    const int rB1 = rA0 + 24;

    for (int kt = 0; kt < nt; kt++) {
        if (kt + 2 < nt) { load_tile(kt + 2, (kt + 2) % 3); CP_COMMIT(); }

        const uint32_t kb = smb + AQ_B + (uint32_t)(kt % 3) * ASTAGE;
        const uint32_t vb = kb + AKV_B;

        // ---- S = Q @ K^T, fp16 acc, both halves (tensor burst) ----
        uint32_t sp0[8][2], sp1[8][2];
#pragma unroll
        for (int j = 0; j < 8; j++) {
            sp0[j][0] = 0; sp0[j][1] = 0;
            sp1[j][0] = 0; sp1[j][1] = 0;
        }
#pragma unroll
        for (int ks = 0; ks < 4; ks++) {
#pragma unroll
            for (int p = 0; p < 4; p++) {
                uint32_t kf[4];
                ldsm4(kf, kb + (uint32_t)(p * 16) * APITCH + ks * 32 + boff);
                mma_h16(sp0[2 * p],     qf0[ks][0], qf0[ks][1], qf0[ks][2], qf0[ks][3], kf[0], kf[1]);
                mma_h16(sp0[2 * p + 1], qf0[ks][0], qf0[ks][1], qf0[ks][2], qf0[ks][3], kf[2], kf[3]);
                mma_h16(sp1[2 * p],     qf1[ks][0], qf1[ks][1], qf1[ks][2], qf1[ks][3], kf[0], kf[1]);
                mma_h16(sp1[2 * p + 1], qf1[ks][0], qf1[ks][1], qf1[ks][2], qf1[ks][3], kf[2], kf[3]);
            }
        }

        // ---- causal mask (packed adds) ----
        const int n0k = kt * 64;
        if (n0k + 63 > rA0) {
#pragma unroll
            for (int j = 0; j < 8; j++) {
                int c0 = n0k + j * 8 + tg * 2;
                uint32_t m0m = ((c0 > rA0) ? MASK_LO : 0u) | ((c0 + 1 > rA0) ? MASK_HI : 0u);
                uint32_t m1m = ((c0 > rA1) ? MASK_LO : 0u) | ((c0 + 1 > rA1) ? MASK_HI : 0u);
                if (m0m) sp0[j][0] = h2add(sp0[j][0], m0m);
                if (m1m) sp0[j][1] = h2add(sp0[j][1], m1m);
            }
        }
        if (n0k + 63 > rB0) {
#pragma unroll
            for (int j = 0; j < 8; j++) {
                int c0 = n0k + j * 8 + tg * 2;
                uint32_t m0m = ((c0 > rB0) ? MASK_LO : 0u) | ((c0 + 1 > rB0) ? MASK_HI : 0u);
                uint32_t m1m = ((c0 > rB1) ? MASK_LO : 0u) | ((c0 + 1 > rB1) ? MASK_HI : 0u);
                if (m0m) sp1[j][0] = h2add(sp1[j][0], m0m);
                if (m1m) sp1[j][1] = h2add(sp1[j][1], m1m);
            }
        }

        // ---- softmax half0 (fma burst) ----
        uint32_t ph0[8][2];
        float alA0, alA1;
        {
            uint32_t v0 = sp0[0][0], v1 = sp0[0][1];
#pragma unroll
            for (int j = 1; j < 8; j++) {
                v0 = h2max(v0, sp0[j][0]);
                v1 = h2max(v1, sp0[j][1]);
            }
            float mx0 = h2max_f(v0), mx1 = h2max_f(v1);
            mx0 = fmaxf(mx0, __shfl_xor_sync(0xffffffffu, mx0, 1));
            mx0 = fmaxf(mx0, __shfl_xor_sync(0xffffffffu, mx0, 2));
            mx1 = fmaxf(mx1, __shfl_xor_sync(0xffffffffu, mx1, 1));
            mx1 = fmaxf(mx1, __shfl_xor_sync(0xffffffffu, mx1, 2));
            float mn0 = fmaxf(mpA0, mx0), mn1 = fmaxf(mpA1, mx1);
            alA0 = exp2f(mpA0 - mn0); alA1 = exp2f(mpA1 - mn1);
            mpA0 = mn0; mpA1 = mn1;
            uint32_t hm0 = pack_h2(mn0, mn0), hm1 = pack_h2(mn1, mn1);
#pragma unroll
            for (int j = 0; j < 8; j++) {
                ph0[j][0] = ex2p(h2sub(sp0[j][0], hm0));
                ph0[j][1] = ex2p(h2sub(sp0[j][1], hm1));
            }
        }

        // ---- rescale O half0 + PV half0 (tensor burst, overlaps softmax1) --
#pragma unroll
        for (int j = 0; j < 8; j++) {
            oacc0[j][0] *= alA0; oacc0[j][1] *= alA0;
            oacc0[j][2] *= alA1; oacc0[j][3] *= alA1;
        }
        float accS0[4] = {0.f, 0.f, 0.f, 0.f};
#pragma unroll
        for (int ks = 0; ks < 4; ks++) {
            uint32_t a00 = ph0[2 * ks][0],     a01 = ph0[2 * ks][1];
            uint32_t a02 = ph0[2 * ks + 1][0], a03 = ph0[2 * ks + 1][1];
            mma_f16(accS0, a00, a01, a02, a03, ONES_H2, ONES_H2);
#pragma unroll
            for (int p = 0; p < 4; p++) {
                uint32_t vf[4];
                ldsm4t(vf, vb + (uint32_t)(ks * 16) * APITCH + p * 32 + aoff);
                mma_f16(oacc0[2 * p],     a00, a01, a02, a03, vf[0], vf[1]);
                mma_f16(oacc0[2 * p + 1], a00, a01, a02, a03, vf[2], vf[3]);
            }
        }
        lsA0 = lsA0 * alA0 + accS0[0];
        lsA1 = lsA1 * alA1 + accS0[2];

        // ---- softmax half1 (fma burst, overlaps PV half0 in flight) ----
        uint32_t ph1[8][2];
        float alB0, alB1;
        {
            uint32_t v0 = sp1[0][0], v1 = sp1[0][1];
#pragma unroll
            for (int j = 1; j < 8; j++) {
                v0 = h2max(v0, sp1[j][0]);
                v1 = h2max(v1, sp1[j][1]);
            }
            float mx0 = h2max_f(v0), mx1 = h2max_f(v1);
            mx0 = fmaxf(mx0, __shfl_xor_sync(0xffffffffu, mx0, 1));
            mx0 = fmaxf(mx0, __shfl_xor_sync(0xffffffffu, mx0, 2));
            mx1 = fmaxf(mx1, __shfl_xor_sync(0xffffffffu, mx1, 1));
            mx1 = fmaxf(mx1, __shfl_xor_sync(0xffffffffu, mx1, 2));
            float mn0 = fmaxf(mpB0, mx0), mn1 = fmaxf(mpB1, mx1);
            alB0 = exp2f(mpB0 - mn0); alB1 = exp2f(mpB1 - mn1);
            mpB0 = mn0; mpB1 = mn1;
            uint32_t hm0 = pack_h2(mn0, mn0), hm1 = pack_h2(mn1, mn1);
#pragma unroll
            for (int j = 0; j < 8; j++) {
                ph1[j][0] = ex2p(h2sub(sp1[j][0], hm0));
                ph1[j][1] = ex2p(h2sub(sp1[j][1], hm1));
            }
        }

        // ---- rescale O half1 + PV half1 (tensor burst) ----
#pragma unroll
        for (int j = 0; j < 8; j++) {
            oacc1[j][0] *= alB0; oacc1[j][1] *= alB0;
            oacc1[j][2] *= alB1; oacc1[j][3] *= alB1;
        }
        float accS1[4] = {0.f, 0.f, 0.f, 0.f};
#pragma unroll
        for (int ks = 0; ks < 4; ks++) {
            uint32_t a10 = ph1[2 * ks][0],     a11 = ph1[2 * ks][1];
            uint32_t a12 = ph1[2 * ks + 1][0], a13 = ph1[2 * ks + 1][1];
            mma_f16(accS1, a10, a11, a12, a13, ONES_H2, ONES_H2);
#pragma unroll
            for (int p = 0; p < 4; p++) {
                uint32_t vf[4];
                ldsm4t(vf, vb + (uint32_t)(ks * 16) * APITCH + p * 32 + aoff);
                mma_f16(oacc1[2 * p],     a10, a11, a12, a13, vf[0], vf[1]);
                mma_f16(oacc1[2 * p + 1], a10, a11, a12, a13, vf[2], vf[3]);
            }
        }
        lsB0 = lsB0 * alB0 + accS1[0];
        lsB1 = lsB1 * alB1 + accS1[2];

        if (kt + 1 < nt) {
            if (kt + 2 < nt) { CP_WAIT1(); } else { CP_WAIT0(); }
            __syncthreads();
        }
    }

    float iA0 = 1.f / lsA0, iA1 = 1.f / lsA1;
    float iB0 = 1.f / lsB0, iB1 = 1.f / lsB1;

    __half* base0 = g_cth + (size_t)(bS + m0 + wid * 32 + g) * D + h * 64;
    __half* base1 = base0 + (size_t)16 * D;
#pragma unroll
    for (int jn = 0; jn < 8; jn++) {
        int off = jn * 8 + tg * 2;
        *(uint32_t*)(base0 + off) = pack_h2(oacc0[jn][0] * iA0, oacc0[jn][1] * iA0);
        *(uint32_t*)(base0 + (size_t)8 * D + off) =
            pack_h2(oacc0[jn][2] * iA1, oacc0[jn][3] * iA1);
        *(uint32_t*)(base1 + off) = pack_h2(oacc1[jn][0] * iB0, oacc1[jn][1] * iB0);
        *(uint32_t*)(base1 + (size_t)8 * D + off) =
            pack_h2(oacc1[jn][2] * iB1, oacc1[jn][3] * iB1);
    }
}

// ---------------------------------------------------------------------------
extern "C" void kernel_launch(void* const* d_in, const int* in_sizes, int n_in,
                              void* d_out, int out_size)
{
    const float* x  = (const float*)d_in[0];
    const float* Wq = (const float*)d_in[1];
    const float* Wk = (const float*)d_in[2];
    const float* Wv = (const float*)d_in[3];
    const float* Wo = (const float*)d_in[4];
    const float* bo = (const float*)d_in[5];
    float* out = (float*)d_out;

    static bool attr_set = false;
    if (!attr_set) {
        cudaFuncSetAttribute(gemm_mma<0>, cudaFuncAttributeMaxDynamicSharedMemorySize, GSMEM);
        cudaFuncSetAttribute(gemm_mma<1>, cudaFuncAttributeMaxDynamicSharedMemorySize, GSMEM);
        cudaFuncSetAttribute(attn_mma,    cudaFuncAttributeMaxDynamicSharedMemorySize, ASMEM);
        attr_set = true;
    }

    conv_all<<<4096 + (MTOT * D / 4) / 256, 256>>>(x, Wq, Wk, Wv, Wo);
    gemm_mma<0><<<dim3(8, 64, 3), 256, GSMEM>>>(nullptr, nullptr);
    attn_mma<<<dim3(SEQ / 128, NHEAD, BATCH), 128, ASMEM>>>();
    gemm_mma<1><<<dim3(8, 64, 1), 256, GSMEM>>>(out, bo);
}